// round 10
// baseline (speedup 1.0000x reference)
#include <cuda_runtime.h>

// Problem sizes (fixed by the reference)
#define LTOT 32768   // B*L = 8*4096
#define EMB  1024    // embed dim (GEMM1 K, GEMM2 N)
#define PRJ  256     // proj dim  (GEMM2 M, GEMM3 K)
#define NC   512     // 2*PRJ (q' | k' concatenated)
#define SEQ  4096    // L per batch

// Scratch (device globals: allocation-free rule)
__device__ float g_C1[(size_t)LTOT * NC];   // exp(x @ [q|k])  64 MB
__device__ float g_kv[8 * PRJ * EMB];       // kv summaries     8 MB
__device__ float g_z[LTOT];                 // row sums of q'

// ---------- tf32 helpers ----------
__device__ __forceinline__ unsigned f2tf(float f) {
    unsigned u;
    asm("cvt.rna.tf32.f32 %0, %1;" : "=r"(u) : "f"(f));
    return u;
}
__device__ __forceinline__ float tfround(float f) { return __uint_as_float(f2tf(f)); }

__device__ __forceinline__ float4 tf4(float4 v) {
    v.x = tfround(v.x); v.y = tfround(v.y); v.z = tfround(v.z); v.w = tfround(v.w);
    return v;
}

// Dekker split: v = h + l with h = RNA-tf32(v), l exact residual (re-rounded)
__device__ __forceinline__ void split4(float4 v, float4& h, float4& l) {
    h.x = tfround(v.x); l.x = tfround(v.x - h.x);
    h.y = tfround(v.y); l.y = tfround(v.y - h.y);
    h.z = tfround(v.z); l.z = tfround(v.z - h.z);
    h.w = tfround(v.w); l.w = tfround(v.w - h.w);
}

// m16n8k8 row.col f32.tf32.tf32.f32
__device__ __forceinline__ void mma8(float* c, const unsigned* a, const unsigned* b) {
    asm volatile(
        "mma.sync.aligned.m16n8k8.row.col.f32.tf32.tf32.f32 "
        "{%0,%1,%2,%3}, {%4,%5,%6,%7}, {%8,%9}, {%0,%1,%2,%3};"
        : "+f"(c[0]), "+f"(c[1]), "+f"(c[2]), "+f"(c[3])
        : "r"(a[0]), "r"(a[1]), "r"(a[2]), "r"(a[3]), "r"(b[0]), "r"(b[1]));
}

// =====================================================================
// Stage 1: C1[m, n] = exp( sum_d x[m,d] * P[d,n] ),  P = [q_proj | k_proj]
// Split-tf32 (3 MMAs) for fp32-grade logits before the exp.
// BM=128, BN=64, BK=16. 8 warps: 4(m) x 2(n), warp tile 32x32.
// grid = (8 n-tiles, 256 m-tiles)  [n fastest -> x rows reused across n]
// =====================================================================
__global__ __launch_bounds__(256) void s1_proj_exp(
    const float* __restrict__ x, const float* __restrict__ qp, const float* __restrict__ kp)
{
    __shared__ float Ah[128 * 20];
    __shared__ float Al[128 * 20];
    __shared__ float Bh[16 * 72];
    __shared__ float Bl[16 * 72];

    const int tid  = threadIdx.x;
    const int warp = tid >> 5, lane = tid & 31;
    const int wm = warp & 3, wn = warp >> 2;
    const int g = lane >> 2, t = lane & 3;

    const int m0 = blockIdx.y * 128;
    const int n0 = blockIdx.x * 64;
    const float* __restrict__ proj = (n0 < PRJ) ? qp : kp;
    const int pc0 = (n0 < PRJ) ? n0 : (n0 - PRJ);

    const int ar = tid >> 2;            // A: rows ar, ar+64 ; cols ac..ac+3
    const int ac = (tid & 3) << 2;
    const int br = tid >> 4;            // B: row br ; cols bc..bc+3
    const int bc = (tid & 15) << 2;

    float acc[2][4][4];
#pragma unroll
    for (int i = 0; i < 2; i++)
#pragma unroll
        for (int j = 0; j < 4; j++)
#pragma unroll
            for (int q = 0; q < 4; q++) acc[i][j][q] = 0.f;

    const float* Ag0 = x + (size_t)(m0 + ar) * EMB + ac;
    const float* Ag1 = x + (size_t)(m0 + ar + 64) * EMB + ac;
    const float* Bg  = proj + (size_t)br * PRJ + pc0 + bc;

    float4 pa0 = *(const float4*)Ag0;
    float4 pa1 = *(const float4*)Ag1;
    float4 pb  = *(const float4*)Bg;

    for (int k0 = 0; k0 < EMB; k0 += 16) {
        float4 h, l;
        split4(pa0, h, l);
        *(float4*)&Ah[ar * 20 + ac] = h;
        *(float4*)&Al[ar * 20 + ac] = l;
        split4(pa1, h, l);
        *(float4*)&Ah[(ar + 64) * 20 + ac] = h;
        *(float4*)&Al[(ar + 64) * 20 + ac] = l;
        split4(pb, h, l);
        *(float4*)&Bh[br * 72 + bc] = h;
        *(float4*)&Bl[br * 72 + bc] = l;
        __syncthreads();

        if (k0 + 16 < EMB) {   // register prefetch of next K tile
            pa0 = *(const float4*)(Ag0 + k0 + 16);
            pa1 = *(const float4*)(Ag1 + k0 + 16);
            pb  = *(const float4*)(Bg + (size_t)(k0 + 16) * PRJ);
        }

#pragma unroll
        for (int ks = 0; ks < 2; ks++) {
            unsigned ah[2][4], aw[2][4], bh[4][2], bw[4][2];
#pragma unroll
            for (int mt = 0; mt < 2; mt++) {
                int r = wm * 32 + mt * 16 + g;
                int c = ks * 8 + t;
                ah[mt][0] = __float_as_uint(Ah[r * 20 + c]);
                ah[mt][1] = __float_as_uint(Ah[(r + 8) * 20 + c]);
                ah[mt][2] = __float_as_uint(Ah[r * 20 + c + 4]);
                ah[mt][3] = __float_as_uint(Ah[(r + 8) * 20 + c + 4]);
                aw[mt][0] = __float_as_uint(Al[r * 20 + c]);
                aw[mt][1] = __float_as_uint(Al[(r + 8) * 20 + c]);
                aw[mt][2] = __float_as_uint(Al[r * 20 + c + 4]);
                aw[mt][3] = __float_as_uint(Al[(r + 8) * 20 + c + 4]);
            }
#pragma unroll
            for (int nt = 0; nt < 4; nt++) {
                int n  = wn * 32 + nt * 8 + g;
                int kk = ks * 8 + t;
                bh[nt][0] = __float_as_uint(Bh[kk * 72 + n]);
                bh[nt][1] = __float_as_uint(Bh[(kk + 4) * 72 + n]);
                bw[nt][0] = __float_as_uint(Bl[kk * 72 + n]);
                bw[nt][1] = __float_as_uint(Bl[(kk + 4) * 72 + n]);
            }
#pragma unroll
            for (int mt = 0; mt < 2; mt++)
#pragma unroll
                for (int nt = 0; nt < 4; nt++) {
                    mma8(acc[mt][nt], ah[mt], bh[nt]);   // hi*hi
                    mma8(acc[mt][nt], ah[mt], bw[nt]);   // hi*lo
                    mma8(acc[mt][nt], aw[mt], bh[nt]);   // lo*hi
                }
        }
        __syncthreads();
    }

#pragma unroll
    for (int mt = 0; mt < 2; mt++) {
        int r = m0 + wm * 32 + mt * 16 + g;
#pragma unroll
        for (int nt = 0; nt < 4; nt++) {
            int c = n0 + wn * 32 + nt * 8 + (t << 1);
            g_C1[(size_t)r * NC + c]           = __expf(acc[mt][nt][0]);
            g_C1[(size_t)r * NC + c + 1]       = __expf(acc[mt][nt][1]);
            g_C1[(size_t)(r + 8) * NC + c]     = __expf(acc[mt][nt][2]);
            g_C1[(size_t)(r + 8) * NC + c + 1] = __expf(acc[mt][nt][3]);
        }
    }
}

// =====================================================================
// z[m] = sum_e q'[m, e]   (one warp per row)
// =====================================================================
__global__ __launch_bounds__(256) void s_z()
{
    int row  = blockIdx.x * 8 + (threadIdx.x >> 5);
    int lane = threadIdx.x & 31;
    const float* p = g_C1 + (size_t)row * NC;
    float s = 0.f;
#pragma unroll
    for (int c = 0; c < 8; c++) s += p[lane + 32 * c];
#pragma unroll
    for (int o = 16; o; o >>= 1) s += __shfl_xor_sync(0xffffffffu, s, o);
    if (lane == 0) g_z[row] = s;
}

// =====================================================================
// Stage 2: kv[b, e, d] = sum_l k'[b, l, e] * x[b, l, d]
// M=256(e), N=1024(d), K=4096(l). Plain tf32.
// BM=64, BN=128, BK=16. 8 warps: 2(m) x 4(n), warp tile 32x32.
// grid = (8 d-tiles, 4 e-tiles, 8 batches) = 256 CTAs
// =====================================================================
__global__ __launch_bounds__(256) void s2_kv(const float* __restrict__ x)
{
    __shared__ float As[16 * 72];    // [l][e], tf32-rounded
    __shared__ float Bs[16 * 136];   // [l][d], tf32-rounded

    const int tid  = threadIdx.x;
    const int warp = tid >> 5, lane = tid & 31;
    const int wm = warp & 1, wn = warp >> 1;
    const int g = lane >> 2, t = lane & 3;
    const int b  = blockIdx.z;
    const int e0 = blockIdx.y * 64;
    const int d0 = blockIdx.x * 128;

    const int alr = tid >> 4;           // 0..15
    const int alc = (tid & 15) << 2;    // 0..60
    const int blr = tid >> 5;           // 0..7 (+8)
    const int blc = (tid & 31) << 2;    // 0..124

    const float* Ag = g_C1 + ((size_t)b * SEQ) * NC + PRJ + e0;   // k' half
    const float* Bg = x + ((size_t)b * SEQ) * EMB + d0;

    float acc[2][4][4];
#pragma unroll
    for (int i = 0; i < 2; i++)
#pragma unroll
        for (int j = 0; j < 4; j++)
#pragma unroll
            for (int q = 0; q < 4; q++) acc[i][j][q] = 0.f;

    float4 pA  = *(const float4*)(Ag + (size_t)alr * NC + alc);
    float4 pB0 = *(const float4*)(Bg + (size_t)blr * EMB + blc);
    float4 pB1 = *(const float4*)(Bg + (size_t)(blr + 8) * EMB + blc);

    for (int l0 = 0; l0 < SEQ; l0 += 16) {
        *(float4*)&As[alr * 72 + alc]        = tf4(pA);
        *(float4*)&Bs[blr * 136 + blc]       = tf4(pB0);
        *(float4*)&Bs[(blr + 8) * 136 + blc] = tf4(pB1);
        __syncthreads();

        if (l0 + 16 < SEQ) {
            pA  = *(const float4*)(Ag + (size_t)(l0 + 16 + alr) * NC + alc);
            pB0 = *(const float4*)(Bg + (size_t)(l0 + 16 + blr) * EMB + blc);
            pB1 = *(const float4*)(Bg + (size_t)(l0 + 24 + blr) * EMB + blc);
        }

#pragma unroll
        for (int ks = 0; ks < 2; ks++) {
            unsigned a[2][4], bf[4][2];
#pragma unroll
            for (int mt = 0; mt < 2; mt++) {
                int e  = wm * 32 + mt * 16 + g;
                int ll = ks * 8 + t;
                a[mt][0] = __float_as_uint(As[ll * 72 + e]);
                a[mt][1] = __float_as_uint(As[ll * 72 + e + 8]);
                a[mt][2] = __float_as_uint(As[(ll + 4) * 72 + e]);
                a[mt][3] = __float_as_uint(As[(ll + 4) * 72 + e + 8]);
            }
#pragma unroll
            for (int nt = 0; nt < 4; nt++) {
                int d  = wn * 32 + nt * 8 + g;
                int ll = ks * 8 + t;
                bf[nt][0] = __float_as_uint(Bs[ll * 136 + d]);
                bf[nt][1] = __float_as_uint(Bs[(ll + 4) * 136 + d]);
            }
#pragma unroll
            for (int mt = 0; mt < 2; mt++)
#pragma unroll
                for (int nt = 0; nt < 4; nt++)
                    mma8(acc[mt][nt], a[mt], bf[nt]);
        }
        __syncthreads();
    }

#pragma unroll
    for (int mt = 0; mt < 2; mt++) {
        int e = e0 + wm * 32 + mt * 16 + g;
#pragma unroll
        for (int nt = 0; nt < 4; nt++) {
            int d = d0 + wn * 32 + nt * 8 + (t << 1);
            g_kv[((size_t)b * PRJ + e) * EMB + d]         = acc[mt][nt][0];
            g_kv[((size_t)b * PRJ + e) * EMB + d + 1]     = acc[mt][nt][1];
            g_kv[((size_t)b * PRJ + e + 8) * EMB + d]     = acc[mt][nt][2];
            g_kv[((size_t)b * PRJ + e + 8) * EMB + d + 1] = acc[mt][nt][3];
        }
    }
}

// =====================================================================
// Stage 3: out[m, d] = (sum_e q'[m, e] * kv[b, e, d]) / (z[m] + 1e-8)
// M=32768, N=1024, K=256. Plain tf32.
// BM=128, BN=128, BK=16. 8 warps: 2(m) x 4(n), warp tile 64x32.
// grid = (8 d-tiles, 256 m-tiles)
// =====================================================================
__global__ __launch_bounds__(256) void s3_out(float* __restrict__ out)
{
    __shared__ float As[128 * 20];   // [m][e]
    __shared__ float Bs[16 * 136];   // [e][d]

    const int tid  = threadIdx.x;
    const int warp = tid >> 5, lane = tid & 31;
    const int wm = warp & 1, wn = warp >> 1;
    const int g = lane >> 2, t = lane & 3;

    const int r0 = blockIdx.y * 128;
    const int d0 = blockIdx.x * 128;
    const int b  = r0 >> 12;                       // r0 / 4096

    const float* Ag = g_C1 + (size_t)r0 * NC;      // q' half (cols 0..255)
    const float* Bg = g_kv + ((size_t)b * PRJ) * EMB + d0;

    const int ar  = tid >> 2;            // rows ar, ar+64
    const int ac  = (tid & 3) << 2;
    const int blr = tid >> 5;            // rows blr, blr+8
    const int blc = (tid & 31) << 2;

    float acc[4][4][4];
#pragma unroll
    for (int i = 0; i < 4; i++)
#pragma unroll
        for (int j = 0; j < 4; j++)
#pragma unroll
            for (int q = 0; q < 4; q++) acc[i][j][q] = 0.f;

    float4 pA0 = *(const float4*)(Ag + (size_t)ar * NC + ac);
    float4 pA1 = *(const float4*)(Ag + (size_t)(ar + 64) * NC + ac);
    float4 pB0 = *(const float4*)(Bg + (size_t)blr * EMB + blc);
    float4 pB1 = *(const float4*)(Bg + (size_t)(blr + 8) * EMB + blc);

    for (int k0 = 0; k0 < PRJ; k0 += 16) {
        *(float4*)&As[ar * 20 + ac]          = tf4(pA0);
        *(float4*)&As[(ar + 64) * 20 + ac]   = tf4(pA1);
        *(float4*)&Bs[blr * 136 + blc]       = tf4(pB0);
        *(float4*)&Bs[(blr + 8) * 136 + blc] = tf4(pB1);
        __syncthreads();

        if (k0 + 16 < PRJ) {
            pA0 = *(const float4*)(Ag + (size_t)ar * NC + k0 + 16 + ac);
            pA1 = *(const float4*)(Ag + (size_t)(ar + 64) * NC + k0 + 16 + ac);
            pB0 = *(const float4*)(Bg + (size_t)(k0 + 16 + blr) * EMB + blc);
            pB1 = *(const float4*)(Bg + (size_t)(k0 + 24 + blr) * EMB + blc);
        }

#pragma unroll
        for (int ks = 0; ks < 2; ks++) {
            unsigned a[4][4], bf[4][2];
#pragma unroll
            for (int mt = 0; mt < 4; mt++) {
                int r = wm * 64 + mt * 16 + g;
                int c = ks * 8 + t;
                a[mt][0] = __float_as_uint(As[r * 20 + c]);
                a[mt][1] = __float_as_uint(As[(r + 8) * 20 + c]);
                a[mt][2] = __float_as_uint(As[r * 20 + c + 4]);
                a[mt][3] = __float_as_uint(As[(r + 8) * 20 + c + 4]);
            }
#pragma unroll
            for (int nt = 0; nt < 4; nt++) {
                int d  = wn * 32 + nt * 8 + g;
                int ll = ks * 8 + t;
                bf[nt][0] = __float_as_uint(Bs[ll * 136 + d]);
                bf[nt][1] = __float_as_uint(Bs[(ll + 4) * 136 + d]);
            }
#pragma unroll
            for (int mt = 0; mt < 4; mt++)
#pragma unroll
                for (int nt = 0; nt < 4; nt++)
                    mma8(acc[mt][nt], a[mt], bf[nt]);
        }
        __syncthreads();
    }

#pragma unroll
    for (int mt = 0; mt < 4; mt++) {
        int rr = r0 + wm * 64 + mt * 16 + g;
        float z0 = 1.f / (g_z[rr] + 1e-8f);
        float z1 = 1.f / (g_z[rr + 8] + 1e-8f);
#pragma unroll
        for (int nt = 0; nt < 4; nt++) {
            int d = d0 + wn * 32 + nt * 8 + (t << 1);
            out[(size_t)rr * EMB + d]           = acc[mt][nt][0] * z0;
            out[(size_t)rr * EMB + d + 1]       = acc[mt][nt][1] * z0;
            out[(size_t)(rr + 8) * EMB + d]     = acc[mt][nt][2] * z1;
            out[(size_t)(rr + 8) * EMB + d + 1] = acc[mt][nt][3] * z1;
        }
    }
}

extern "C" void kernel_launch(void* const* d_in, const int* in_sizes, int n_in,
                              void* d_out, int out_size)
{
    (void)in_sizes; (void)n_in; (void)out_size;
    const float* x  = (const float*)d_in[0];
    const float* qp = (const float*)d_in[1];
    const float* kp = (const float*)d_in[2];
    float* out = (float*)d_out;

    s1_proj_exp<<<dim3(8, 256), 256>>>(x, qp, kp);  // logits + exp
    s_z<<<4096, 256>>>();                           // row sums of q'
    s2_kv<<<dim3(8, 4, 8), 256>>>(x);               // kv summaries
    s3_out<<<dim3(8, 256), 256>>>(out);             // numerator + normalize
}

// round 14
// speedup vs baseline: 1.2604x; 1.2604x over previous
#include <cuda_runtime.h>

// Problem sizes (fixed by the reference)
#define LTOT 32768   // B*L = 8*4096
#define EMB  1024    // embed dim (GEMM1 K, GEMM2 N)
#define PRJ  256     // proj dim  (GEMM2 M, GEMM3 K)
#define NC   512     // 2*PRJ (q' | k' concatenated)
#define SEQ  4096    // L per batch

// Scratch (device globals: allocation-free rule)
__device__ float g_C1[(size_t)LTOT * NC];   // exp(x @ [q|k])  64 MB
__device__ float g_kv[8 * PRJ * EMB];       // kv summaries     8 MB
__device__ float g_z[LTOT];                 // row sums of q'

// ---------- tf32 helpers ----------
__device__ __forceinline__ unsigned f2tf(float f) {
    unsigned u;
    asm("cvt.rna.tf32.f32 %0, %1;" : "=r"(u) : "f"(f));
    return u;
}
__device__ __forceinline__ float tfround(float f) { return __uint_as_float(f2tf(f)); }

__device__ __forceinline__ float4 tf4(float4 v) {
    v.x = tfround(v.x); v.y = tfround(v.y); v.z = tfround(v.z); v.w = tfround(v.w);
    return v;
}

// Dekker split: v = h + l with h = RNA-tf32(v), l exact residual (re-rounded)
__device__ __forceinline__ void split4(float4 v, float4& h, float4& l) {
    h.x = tfround(v.x); l.x = tfround(v.x - h.x);
    h.y = tfround(v.y); l.y = tfround(v.y - h.y);
    h.z = tfround(v.z); l.z = tfround(v.z - h.z);
    h.w = tfround(v.w); l.w = tfround(v.w - h.w);
}

// m16n8k8 row.col f32.tf32.tf32.f32
__device__ __forceinline__ void mma8(float* c, const unsigned* a, const unsigned* b) {
    asm volatile(
        "mma.sync.aligned.m16n8k8.row.col.f32.tf32.tf32.f32 "
        "{%0,%1,%2,%3}, {%4,%5,%6,%7}, {%8,%9}, {%0,%1,%2,%3};"
        : "+f"(c[0]), "+f"(c[1]), "+f"(c[2]), "+f"(c[3])
        : "r"(a[0]), "r"(a[1]), "r"(a[2]), "r"(a[3]), "r"(b[0]), "r"(b[1]));
}

// =====================================================================
// Stage 1: C1[m, n] = exp( sum_d x[m,d] * P[d,n] ),  P = [q_proj | k_proj]
// A-split tf32 (2 MMAs): logit error = proj rounding only (~3.5e-4 cal.)
// BM=128, BN=64, BK=16. 8 warps: 4(m) x 2(n), warp tile 32x32.
// grid = (8 n-tiles, 256 m-tiles)  [n fastest -> x rows reused across n]
// =====================================================================
__global__ __launch_bounds__(256) void s1_proj_exp(
    const float* __restrict__ x, const float* __restrict__ qp, const float* __restrict__ kp)
{
    __shared__ float Ah[128 * 20];
    __shared__ float Al[128 * 20];
    __shared__ float Bh[16 * 72];

    const int tid  = threadIdx.x;
    const int warp = tid >> 5, lane = tid & 31;
    const int wm = warp & 3, wn = warp >> 2;
    const int g = lane >> 2, t = lane & 3;

    const int m0 = blockIdx.y * 128;
    const int n0 = blockIdx.x * 64;
    const float* __restrict__ proj = (n0 < PRJ) ? qp : kp;
    const int pc0 = (n0 < PRJ) ? n0 : (n0 - PRJ);

    const int ar = tid >> 2;            // A: rows ar, ar+64 ; cols ac..ac+3
    const int ac = (tid & 3) << 2;
    const int br = tid >> 4;            // B: row br ; cols bc..bc+3
    const int bc = (tid & 15) << 2;

    float acc[2][4][4];
#pragma unroll
    for (int i = 0; i < 2; i++)
#pragma unroll
        for (int j = 0; j < 4; j++)
#pragma unroll
            for (int q = 0; q < 4; q++) acc[i][j][q] = 0.f;

    const float* Ag0 = x + (size_t)(m0 + ar) * EMB + ac;
    const float* Ag1 = x + (size_t)(m0 + ar + 64) * EMB + ac;
    const float* Bg  = proj + (size_t)br * PRJ + pc0 + bc;

    float4 pa0 = *(const float4*)Ag0;
    float4 pa1 = *(const float4*)Ag1;
    float4 pb  = *(const float4*)Bg;

    for (int k0 = 0; k0 < EMB; k0 += 16) {
        float4 h, l;
        split4(pa0, h, l);
        *(float4*)&Ah[ar * 20 + ac] = h;
        *(float4*)&Al[ar * 20 + ac] = l;
        split4(pa1, h, l);
        *(float4*)&Ah[(ar + 64) * 20 + ac] = h;
        *(float4*)&Al[(ar + 64) * 20 + ac] = l;
        *(float4*)&Bh[br * 72 + bc] = tf4(pb);
        __syncthreads();

        if (k0 + 16 < EMB) {   // register prefetch of next K tile
            pa0 = *(const float4*)(Ag0 + k0 + 16);
            pa1 = *(const float4*)(Ag1 + k0 + 16);
            pb  = *(const float4*)(Bg + (size_t)(k0 + 16) * PRJ);
        }

#pragma unroll
        for (int ks = 0; ks < 2; ks++) {
            unsigned ah[2][4], aw[2][4], bh[4][2];
#pragma unroll
            for (int mt = 0; mt < 2; mt++) {
                int r = wm * 32 + mt * 16 + g;
                int c = ks * 8 + t;
                ah[mt][0] = __float_as_uint(Ah[r * 20 + c]);
                ah[mt][1] = __float_as_uint(Ah[(r + 8) * 20 + c]);
                ah[mt][2] = __float_as_uint(Ah[r * 20 + c + 4]);
                ah[mt][3] = __float_as_uint(Ah[(r + 8) * 20 + c + 4]);
                aw[mt][0] = __float_as_uint(Al[r * 20 + c]);
                aw[mt][1] = __float_as_uint(Al[(r + 8) * 20 + c]);
                aw[mt][2] = __float_as_uint(Al[r * 20 + c + 4]);
                aw[mt][3] = __float_as_uint(Al[(r + 8) * 20 + c + 4]);
            }
#pragma unroll
            for (int nt = 0; nt < 4; nt++) {
                int n  = wn * 32 + nt * 8 + g;
                int kk = ks * 8 + t;
                bh[nt][0] = __float_as_uint(Bh[kk * 72 + n]);
                bh[nt][1] = __float_as_uint(Bh[(kk + 4) * 72 + n]);
            }
#pragma unroll
            for (int mt = 0; mt < 2; mt++)
#pragma unroll
                for (int nt = 0; nt < 4; nt++) {
                    mma8(acc[mt][nt], ah[mt], bh[nt]);   // hi * B
                    mma8(acc[mt][nt], aw[mt], bh[nt]);   // lo * B
                }
        }
        __syncthreads();
    }

#pragma unroll
    for (int mt = 0; mt < 2; mt++) {
        int r = m0 + wm * 32 + mt * 16 + g;
#pragma unroll
        for (int nt = 0; nt < 4; nt++) {
            int c = n0 + wn * 32 + nt * 8 + (t << 1);
            g_C1[(size_t)r * NC + c]           = __expf(acc[mt][nt][0]);
            g_C1[(size_t)r * NC + c + 1]       = __expf(acc[mt][nt][1]);
            g_C1[(size_t)(r + 8) * NC + c]     = __expf(acc[mt][nt][2]);
            g_C1[(size_t)(r + 8) * NC + c + 1] = __expf(acc[mt][nt][3]);
        }
    }
}

// =====================================================================
// z[m] = sum_e q'[m, e]   (one warp per row)
// =====================================================================
__global__ __launch_bounds__(256) void s_z()
{
    int row  = blockIdx.x * 8 + (threadIdx.x >> 5);
    int lane = threadIdx.x & 31;
    const float* p = g_C1 + (size_t)row * NC;
    float s = 0.f;
#pragma unroll
    for (int c = 0; c < 8; c++) s += p[lane + 32 * c];
#pragma unroll
    for (int o = 16; o; o >>= 1) s += __shfl_xor_sync(0xffffffffu, s, o);
    if (lane == 0) g_z[row] = s;
}

// =====================================================================
// Stage 2: kv[b, e, d] = sum_l k'[b, l, e] * x[b, l, d]
// M=256(e), N=1024(d), K=4096(l). Plain tf32.
// BM=64, BN=128, BK=16. 8 warps: 2(m) x 4(n), warp tile 32x32.
// grid = (8 d-tiles, 4 e-tiles, 8 batches) = 256 CTAs
// =====================================================================
__global__ __launch_bounds__(256) void s2_kv(const float* __restrict__ x)
{
    __shared__ float As[16 * 72];    // [l][e], tf32-rounded
    __shared__ float Bs[16 * 136];   // [l][d], tf32-rounded

    const int tid  = threadIdx.x;
    const int warp = tid >> 5, lane = tid & 31;
    const int wm = warp & 1, wn = warp >> 1;
    const int g = lane >> 2, t = lane & 3;
    const int b  = blockIdx.z;
    const int e0 = blockIdx.y * 64;
    const int d0 = blockIdx.x * 128;

    const int alr = tid >> 4;           // 0..15
    const int alc = (tid & 15) << 2;    // 0..60
    const int blr = tid >> 5;           // 0..7 (+8)
    const int blc = (tid & 31) << 2;    // 0..124

    const float* Ag = g_C1 + ((size_t)b * SEQ) * NC + PRJ + e0;   // k' half
    const float* Bg = x + ((size_t)b * SEQ) * EMB + d0;

    float acc[2][4][4];
#pragma unroll
    for (int i = 0; i < 2; i++)
#pragma unroll
        for (int j = 0; j < 4; j++)
#pragma unroll
            for (int q = 0; q < 4; q++) acc[i][j][q] = 0.f;

    float4 pA  = *(const float4*)(Ag + (size_t)alr * NC + alc);
    float4 pB0 = *(const float4*)(Bg + (size_t)blr * EMB + blc);
    float4 pB1 = *(const float4*)(Bg + (size_t)(blr + 8) * EMB + blc);

    for (int l0 = 0; l0 < SEQ; l0 += 16) {
        *(float4*)&As[alr * 72 + alc]        = tf4(pA);
        *(float4*)&Bs[blr * 136 + blc]       = tf4(pB0);
        *(float4*)&Bs[(blr + 8) * 136 + blc] = tf4(pB1);
        __syncthreads();

        if (l0 + 16 < SEQ) {
            pA  = *(const float4*)(Ag + (size_t)(l0 + 16 + alr) * NC + alc);
            pB0 = *(const float4*)(Bg + (size_t)(l0 + 16 + blr) * EMB + blc);
            pB1 = *(const float4*)(Bg + (size_t)(l0 + 24 + blr) * EMB + blc);
        }

#pragma unroll
        for (int ks = 0; ks < 2; ks++) {
            unsigned a[2][4], bf[4][2];
#pragma unroll
            for (int mt = 0; mt < 2; mt++) {
                int e  = wm * 32 + mt * 16 + g;
                int ll = ks * 8 + t;
                a[mt][0] = __float_as_uint(As[ll * 72 + e]);
                a[mt][1] = __float_as_uint(As[ll * 72 + e + 8]);
                a[mt][2] = __float_as_uint(As[(ll + 4) * 72 + e]);
                a[mt][3] = __float_as_uint(As[(ll + 4) * 72 + e + 8]);
            }
#pragma unroll
            for (int nt = 0; nt < 4; nt++) {
                int d  = wn * 32 + nt * 8 + g;
                int ll = ks * 8 + t;
                bf[nt][0] = __float_as_uint(Bs[ll * 136 + d]);
                bf[nt][1] = __float_as_uint(Bs[(ll + 4) * 136 + d]);
            }
#pragma unroll
            for (int mt = 0; mt < 2; mt++)
#pragma unroll
                for (int nt = 0; nt < 4; nt++)
                    mma8(acc[mt][nt], a[mt], bf[nt]);
        }
        __syncthreads();
    }

#pragma unroll
    for (int mt = 0; mt < 2; mt++) {
        int e = e0 + wm * 32 + mt * 16 + g;
#pragma unroll
        for (int nt = 0; nt < 4; nt++) {
            int d = d0 + wn * 32 + nt * 8 + (t << 1);
            g_kv[((size_t)b * PRJ + e) * EMB + d]         = acc[mt][nt][0];
            g_kv[((size_t)b * PRJ + e) * EMB + d + 1]     = acc[mt][nt][1];
            g_kv[((size_t)b * PRJ + e + 8) * EMB + d]     = acc[mt][nt][2];
            g_kv[((size_t)b * PRJ + e + 8) * EMB + d + 1] = acc[mt][nt][3];
        }
    }
}

// =====================================================================
// Stage 3: out[m, d] = (sum_e q'[m, e] * kv[b, e, d]) / (z[m] + 1e-8)
// M=32768, N=1024, K=256. Plain tf32.
// BM=128, BN=128, BK=16. 8 warps: 2(m) x 4(n), warp tile 64x32.
// grid = (8 d-tiles, 256 m-tiles)
// =====================================================================
__global__ __launch_bounds__(256) void s3_out(float* __restrict__ out)
{
    __shared__ float As[128 * 20];   // [m][e]
    __shared__ float Bs[16 * 136];   // [e][d]

    const int tid  = threadIdx.x;
    const int warp = tid >> 5, lane = tid & 31;
    const int wm = warp & 1, wn = warp >> 1;
    const int g = lane >> 2, t = lane & 3;

    const int r0 = blockIdx.y * 128;
    const int d0 = blockIdx.x * 128;
    const int b  = r0 >> 12;                       // r0 / 4096

    const float* Ag = g_C1 + (size_t)r0 * NC;      // q' half (cols 0..255)
    const float* Bg = g_kv + ((size_t)b * PRJ) * EMB + d0;

    const int ar  = tid >> 2;            // rows ar, ar+64
    const int ac  = (tid & 3) << 2;
    const int blr = tid >> 5;            // rows blr, blr+8
    const int blc = (tid & 31) << 2;

    float acc[4][4][4];
#pragma unroll
    for (int i = 0; i < 4; i++)
#pragma unroll
        for (int j = 0; j < 4; j++)
#pragma unroll
            for (int q = 0; q < 4; q++) acc[i][j][q] = 0.f;

    float4 pA0 = *(const float4*)(Ag + (size_t)ar * NC + ac);
    float4 pA1 = *(const float4*)(Ag + (size_t)(ar + 64) * NC + ac);
    float4 pB0 = *(const float4*)(Bg + (size_t)blr * EMB + blc);
    float4 pB1 = *(const float4*)(Bg + (size_t)(blr + 8) * EMB + blc);

    for (int k0 = 0; k0 < PRJ; k0 += 16) {
        *(float4*)&As[ar * 20 + ac]          = tf4(pA0);
        *(float4*)&As[(ar + 64) * 20 + ac]   = tf4(pA1);
        *(float4*)&Bs[blr * 136 + blc]       = tf4(pB0);
        *(float4*)&Bs[(blr + 8) * 136 + blc] = tf4(pB1);
        __syncthreads();

        if (k0 + 16 < PRJ) {
            pA0 = *(const float4*)(Ag + (size_t)ar * NC + k0 + 16 + ac);
            pA1 = *(const float4*)(Ag + (size_t)(ar + 64) * NC + k0 + 16 + ac);
            pB0 = *(const float4*)(Bg + (size_t)(k0 + 16 + blr) * EMB + blc);
            pB1 = *(const float4*)(Bg + (size_t)(k0 + 24 + blr) * EMB + blc);
        }

#pragma unroll
        for (int ks = 0; ks < 2; ks++) {
            unsigned a[4][4], bf[4][2];
#pragma unroll
            for (int mt = 0; mt < 4; mt++) {
                int r = wm * 64 + mt * 16 + g;
                int c = ks * 8 + t;
                a[mt][0] = __float_as_uint(As[r * 20 + c]);
                a[mt][1] = __float_as_uint(As[(r + 8) * 20 + c]);
                a[mt][2] = __float_as_uint(As[r * 20 + c + 4]);
                a[mt][3] = __float_as_uint(As[(r + 8) * 20 + c + 4]);
            }
#pragma unroll
            for (int nt = 0; nt < 4; nt++) {
                int d  = wn * 32 + nt * 8 + g;
                int ll = ks * 8 + t;
                bf[nt][0] = __float_as_uint(Bs[ll * 136 + d]);
                bf[nt][1] = __float_as_uint(Bs[(ll + 4) * 136 + d]);
            }
#pragma unroll
            for (int mt = 0; mt < 4; mt++)
#pragma unroll
                for (int nt = 0; nt < 4; nt++)
                    mma8(acc[mt][nt], a[mt], bf[nt]);
        }
        __syncthreads();
    }

#pragma unroll
    for (int mt = 0; mt < 4; mt++) {
        int rr = r0 + wm * 64 + mt * 16 + g;
        float z0 = 1.f / (g_z[rr] + 1e-8f);
        float z1 = 1.f / (g_z[rr + 8] + 1e-8f);
#pragma unroll
        for (int nt = 0; nt < 4; nt++) {
            int d = d0 + wn * 32 + nt * 8 + (t << 1);
            out[(size_t)rr * EMB + d]           = acc[mt][nt][0] * z0;
            out[(size_t)rr * EMB + d + 1]       = acc[mt][nt][1] * z0;
            out[(size_t)(rr + 8) * EMB + d]     = acc[mt][nt][2] * z1;
            out[(size_t)(rr + 8) * EMB + d + 1] = acc[mt][nt][3] * z1;
        }
    }
}

extern "C" void kernel_launch(void* const* d_in, const int* in_sizes, int n_in,
                              void* d_out, int out_size)
{
    (void)in_sizes; (void)n_in; (void)out_size;
    const float* x  = (const float*)d_in[0];
    const float* qp = (const float*)d_in[1];
    const float* kp = (const float*)d_in[2];
    float* out = (float*)d_out;

    s1_proj_exp<<<dim3(8, 256), 256>>>(x, qp, kp);  // logits + exp
    s_z<<<4096, 256>>>();                           // row sums of q'
    s2_kv<<<dim3(8, 4, 8), 256>>>(x);               // kv summaries
    s3_out<<<dim3(8, 256), 256>>>(out);             // numerator + normalize
}

// round 15
// speedup vs baseline: 1.4550x; 1.1544x over previous
#include <cuda_runtime.h>

// Problem sizes (fixed by the reference)
#define LTOT 32768   // B*L = 8*4096
#define EMB  1024    // embed dim (GEMM1 K, GEMM2 N)
#define PRJ  256     // proj dim  (GEMM2 M, GEMM3 K)
#define NC   512     // 2*PRJ (q' | k' concatenated)
#define SEQ  4096    // L per batch

// Scratch (device globals: allocation-free rule)
__device__ float g_C1[(size_t)LTOT * NC];   // exp(x @ [q|k])  64 MB
__device__ float g_kv[8 * PRJ * EMB];       // kv summaries     8 MB
__device__ float g_z[LTOT];                 // row sums of q'

// ---------- tf32 helpers ----------
__device__ __forceinline__ unsigned f2tf(float f) {
    unsigned u;
    asm("cvt.rna.tf32.f32 %0, %1;" : "=r"(u) : "f"(f));
    return u;
}
__device__ __forceinline__ float tfround(float f) { return __uint_as_float(f2tf(f)); }

__device__ __forceinline__ float4 tf4(float4 v) {
    v.x = tfround(v.x); v.y = tfround(v.y); v.z = tfround(v.z); v.w = tfround(v.w);
    return v;
}

// m16n8k8 row.col f32.tf32.tf32.f32
__device__ __forceinline__ void mma8(float* c, const unsigned* a, const unsigned* b) {
    asm volatile(
        "mma.sync.aligned.m16n8k8.row.col.f32.tf32.tf32.f32 "
        "{%0,%1,%2,%3}, {%4,%5,%6,%7}, {%8,%9}, {%0,%1,%2,%3};"
        : "+f"(c[0]), "+f"(c[1]), "+f"(c[2]), "+f"(c[3])
        : "r"(a[0]), "r"(a[1]), "r"(a[2]), "r"(a[3]), "r"(b[0]), "r"(b[1]));
}

// =====================================================================
// Stage 1: C1[m, n] = exp( sum_d x[m,d] * P[d,n] ),  P = [q_proj | k_proj]
// Plain tf32 (1 MMA). Calibrated logit error: A-round 4.7e-4 + B-round
// 4.7e-4 (RSS) -> total pipeline rel_err ~7.6e-4 (threshold 1e-3).
// BM=128, BN=64, BK=16. 8 warps: 4(m) x 2(n), warp tile 32x32.
// grid = (8 n-tiles, 256 m-tiles)  [n fastest -> x rows reused across n]
// =====================================================================
__global__ __launch_bounds__(256) void s1_proj_exp(
    const float* __restrict__ x, const float* __restrict__ qp, const float* __restrict__ kp)
{
    __shared__ float Ah[128 * 20];
    __shared__ float Bh[16 * 72];

    const int tid  = threadIdx.x;
    const int warp = tid >> 5, lane = tid & 31;
    const int wm = warp & 3, wn = warp >> 2;
    const int g = lane >> 2, t = lane & 3;

    const int m0 = blockIdx.y * 128;
    const int n0 = blockIdx.x * 64;
    const float* __restrict__ proj = (n0 < PRJ) ? qp : kp;
    const int pc0 = (n0 < PRJ) ? n0 : (n0 - PRJ);

    const int ar = tid >> 2;            // A: rows ar, ar+64 ; cols ac..ac+3
    const int ac = (tid & 3) << 2;
    const int br = tid >> 4;            // B: row br ; cols bc..bc+3
    const int bc = (tid & 15) << 2;

    float acc[2][4][4];
#pragma unroll
    for (int i = 0; i < 2; i++)
#pragma unroll
        for (int j = 0; j < 4; j++)
#pragma unroll
            for (int q = 0; q < 4; q++) acc[i][j][q] = 0.f;

    const float* Ag0 = x + (size_t)(m0 + ar) * EMB + ac;
    const float* Ag1 = x + (size_t)(m0 + ar + 64) * EMB + ac;
    const float* Bg  = proj + (size_t)br * PRJ + pc0 + bc;

    float4 pa0 = *(const float4*)Ag0;
    float4 pa1 = *(const float4*)Ag1;
    float4 pb  = *(const float4*)Bg;

    for (int k0 = 0; k0 < EMB; k0 += 16) {
        *(float4*)&Ah[ar * 20 + ac]        = tf4(pa0);
        *(float4*)&Ah[(ar + 64) * 20 + ac] = tf4(pa1);
        *(float4*)&Bh[br * 72 + bc]        = tf4(pb);
        __syncthreads();

        if (k0 + 16 < EMB) {   // register prefetch of next K tile
            pa0 = *(const float4*)(Ag0 + k0 + 16);
            pa1 = *(const float4*)(Ag1 + k0 + 16);
            pb  = *(const float4*)(Bg + (size_t)(k0 + 16) * PRJ);
        }

#pragma unroll
        for (int ks = 0; ks < 2; ks++) {
            unsigned ah[2][4], bh[4][2];
#pragma unroll
            for (int mt = 0; mt < 2; mt++) {
                int r = wm * 32 + mt * 16 + g;
                int c = ks * 8 + t;
                ah[mt][0] = __float_as_uint(Ah[r * 20 + c]);
                ah[mt][1] = __float_as_uint(Ah[(r + 8) * 20 + c]);
                ah[mt][2] = __float_as_uint(Ah[r * 20 + c + 4]);
                ah[mt][3] = __float_as_uint(Ah[(r + 8) * 20 + c + 4]);
            }
#pragma unroll
            for (int nt = 0; nt < 4; nt++) {
                int n  = wn * 32 + nt * 8 + g;
                int kk = ks * 8 + t;
                bh[nt][0] = __float_as_uint(Bh[kk * 72 + n]);
                bh[nt][1] = __float_as_uint(Bh[(kk + 4) * 72 + n]);
            }
#pragma unroll
            for (int mt = 0; mt < 2; mt++)
#pragma unroll
                for (int nt = 0; nt < 4; nt++)
                    mma8(acc[mt][nt], ah[mt], bh[nt]);
        }
        __syncthreads();
    }

#pragma unroll
    for (int mt = 0; mt < 2; mt++) {
        int r = m0 + wm * 32 + mt * 16 + g;
#pragma unroll
        for (int nt = 0; nt < 4; nt++) {
            int c = n0 + wn * 32 + nt * 8 + (t << 1);
            g_C1[(size_t)r * NC + c]           = __expf(acc[mt][nt][0]);
            g_C1[(size_t)r * NC + c + 1]       = __expf(acc[mt][nt][1]);
            g_C1[(size_t)(r + 8) * NC + c]     = __expf(acc[mt][nt][2]);
            g_C1[(size_t)(r + 8) * NC + c + 1] = __expf(acc[mt][nt][3]);
        }
    }
}

// =====================================================================
// z[m] = sum_e q'[m, e]   (one warp per row)
// =====================================================================
__global__ __launch_bounds__(256) void s_z()
{
    int row  = blockIdx.x * 8 + (threadIdx.x >> 5);
    int lane = threadIdx.x & 31;
    const float* p = g_C1 + (size_t)row * NC;
    float s = 0.f;
#pragma unroll
    for (int c = 0; c < 8; c++) s += p[lane + 32 * c];
#pragma unroll
    for (int o = 16; o; o >>= 1) s += __shfl_xor_sync(0xffffffffu, s, o);
    if (lane == 0) g_z[row] = s;
}

// =====================================================================
// Stage 2: kv[b, e, d] = sum_l k'[b, l, e] * x[b, l, d]
// M=256(e), N=1024(d), K=4096(l). Plain tf32.
// BM=64, BN=128, BK=16. 8 warps: 2(m) x 4(n), warp tile 32x32.
// grid = (8 d-tiles, 4 e-tiles, 8 batches) = 256 CTAs
// =====================================================================
__global__ __launch_bounds__(256) void s2_kv(const float* __restrict__ x)
{
    __shared__ float As[16 * 72];    // [l][e], tf32-rounded
    __shared__ float Bs[16 * 136];   // [l][d], tf32-rounded

    const int tid  = threadIdx.x;
    const int warp = tid >> 5, lane = tid & 31;
    const int wm = warp & 1, wn = warp >> 1;
    const int g = lane >> 2, t = lane & 3;
    const int b  = blockIdx.z;
    const int e0 = blockIdx.y * 64;
    const int d0 = blockIdx.x * 128;

    const int alr = tid >> 4;           // 0..15
    const int alc = (tid & 15) << 2;    // 0..60
    const int blr = tid >> 5;           // 0..7 (+8)
    const int blc = (tid & 31) << 2;    // 0..124

    const float* Ag = g_C1 + ((size_t)b * SEQ) * NC + PRJ + e0;   // k' half
    const float* Bg = x + ((size_t)b * SEQ) * EMB + d0;

    float acc[2][4][4];
#pragma unroll
    for (int i = 0; i < 2; i++)
#pragma unroll
        for (int j = 0; j < 4; j++)
#pragma unroll
            for (int q = 0; q < 4; q++) acc[i][j][q] = 0.f;

    float4 pA  = *(const float4*)(Ag + (size_t)alr * NC + alc);
    float4 pB0 = *(const float4*)(Bg + (size_t)blr * EMB + blc);
    float4 pB1 = *(const float4*)(Bg + (size_t)(blr + 8) * EMB + blc);

    for (int l0 = 0; l0 < SEQ; l0 += 16) {
        *(float4*)&As[alr * 72 + alc]        = tf4(pA);
        *(float4*)&Bs[blr * 136 + blc]       = tf4(pB0);
        *(float4*)&Bs[(blr + 8) * 136 + blc] = tf4(pB1);
        __syncthreads();

        if (l0 + 16 < SEQ) {
            pA  = *(const float4*)(Ag + (size_t)(l0 + 16 + alr) * NC + alc);
            pB0 = *(const float4*)(Bg + (size_t)(l0 + 16 + blr) * EMB + blc);
            pB1 = *(const float4*)(Bg + (size_t)(l0 + 24 + blr) * EMB + blc);
        }

#pragma unroll
        for (int ks = 0; ks < 2; ks++) {
            unsigned a[2][4], bf[4][2];
#pragma unroll
            for (int mt = 0; mt < 2; mt++) {
                int e  = wm * 32 + mt * 16 + g;
                int ll = ks * 8 + t;
                a[mt][0] = __float_as_uint(As[ll * 72 + e]);
                a[mt][1] = __float_as_uint(As[ll * 72 + e + 8]);
                a[mt][2] = __float_as_uint(As[(ll + 4) * 72 + e]);
                a[mt][3] = __float_as_uint(As[(ll + 4) * 72 + e + 8]);
            }
#pragma unroll
            for (int nt = 0; nt < 4; nt++) {
                int d  = wn * 32 + nt * 8 + g;
                int ll = ks * 8 + t;
                bf[nt][0] = __float_as_uint(Bs[ll * 136 + d]);
                bf[nt][1] = __float_as_uint(Bs[(ll + 4) * 136 + d]);
            }
#pragma unroll
            for (int mt = 0; mt < 2; mt++)
#pragma unroll
                for (int nt = 0; nt < 4; nt++)
                    mma8(acc[mt][nt], a[mt], bf[nt]);
        }
        __syncthreads();
    }

#pragma unroll
    for (int mt = 0; mt < 2; mt++) {
        int e = e0 + wm * 32 + mt * 16 + g;
#pragma unroll
        for (int nt = 0; nt < 4; nt++) {
            int d = d0 + wn * 32 + nt * 8 + (t << 1);
            g_kv[((size_t)b * PRJ + e) * EMB + d]         = acc[mt][nt][0];
            g_kv[((size_t)b * PRJ + e) * EMB + d + 1]     = acc[mt][nt][1];
            g_kv[((size_t)b * PRJ + e + 8) * EMB + d]     = acc[mt][nt][2];
            g_kv[((size_t)b * PRJ + e + 8) * EMB + d + 1] = acc[mt][nt][3];
        }
    }
}

// =====================================================================
// Stage 3: out[m, d] = (sum_e q'[m, e] * kv[b, e, d]) / (z[m] + 1e-8)
// M=32768, N=1024, K=256. Plain tf32.
// BM=128, BN=128, BK=16. 8 warps: 2(m) x 4(n), warp tile 64x32.
// grid = (8 d-tiles, 256 m-tiles)
// =====================================================================
__global__ __launch_bounds__(256) void s3_out(float* __restrict__ out)
{
    __shared__ float As[128 * 20];   // [m][e]
    __shared__ float Bs[16 * 136];   // [e][d]

    const int tid  = threadIdx.x;
    const int warp = tid >> 5, lane = tid & 31;
    const int wm = warp & 1, wn = warp >> 1;
    const int g = lane >> 2, t = lane & 3;

    const int r0 = blockIdx.y * 128;
    const int d0 = blockIdx.x * 128;
    const int b  = r0 >> 12;                       // r0 / 4096

    const float* Ag = g_C1 + (size_t)r0 * NC;      // q' half (cols 0..255)
    const float* Bg = g_kv + ((size_t)b * PRJ) * EMB + d0;

    const int ar  = tid >> 2;            // rows ar, ar+64
    const int ac  = (tid & 3) << 2;
    const int blr = tid >> 5;            // rows blr, blr+8
    const int blc = (tid & 31) << 2;

    float acc[4][4][4];
#pragma unroll
    for (int i = 0; i < 4; i++)
#pragma unroll
        for (int j = 0; j < 4; j++)
#pragma unroll
            for (int q = 0; q < 4; q++) acc[i][j][q] = 0.f;

    float4 pA0 = *(const float4*)(Ag + (size_t)ar * NC + ac);
    float4 pA1 = *(const float4*)(Ag + (size_t)(ar + 64) * NC + ac);
    float4 pB0 = *(const float4*)(Bg + (size_t)blr * EMB + blc);
    float4 pB1 = *(const float4*)(Bg + (size_t)(blr + 8) * EMB + blc);

    for (int k0 = 0; k0 < PRJ; k0 += 16) {
        *(float4*)&As[ar * 20 + ac]          = tf4(pA0);
        *(float4*)&As[(ar + 64) * 20 + ac]   = tf4(pA1);
        *(float4*)&Bs[blr * 136 + blc]       = tf4(pB0);
        *(float4*)&Bs[(blr + 8) * 136 + blc] = tf4(pB1);
        __syncthreads();

        if (k0 + 16 < PRJ) {
            pA0 = *(const float4*)(Ag + (size_t)ar * NC + k0 + 16 + ac);
            pA1 = *(const float4*)(Ag + (size_t)(ar + 64) * NC + k0 + 16 + ac);
            pB0 = *(const float4*)(Bg + (size_t)(k0 + 16 + blr) * EMB + blc);
            pB1 = *(const float4*)(Bg + (size_t)(k0 + 24 + blr) * EMB + blc);
        }

#pragma unroll
        for (int ks = 0; ks < 2; ks++) {
            unsigned a[4][4], bf[4][2];
#pragma unroll
            for (int mt = 0; mt < 4; mt++) {
                int r = wm * 64 + mt * 16 + g;
                int c = ks * 8 + t;
                a[mt][0] = __float_as_uint(As[r * 20 + c]);
                a[mt][1] = __float_as_uint(As[(r + 8) * 20 + c]);
                a[mt][2] = __float_as_uint(As[r * 20 + c + 4]);
                a[mt][3] = __float_as_uint(As[(r + 8) * 20 + c + 4]);
            }
#pragma unroll
            for (int nt = 0; nt < 4; nt++) {
                int d  = wn * 32 + nt * 8 + g;
                int ll = ks * 8 + t;
                bf[nt][0] = __float_as_uint(Bs[ll * 136 + d]);
                bf[nt][1] = __float_as_uint(Bs[(ll + 4) * 136 + d]);
            }
#pragma unroll
            for (int mt = 0; mt < 4; mt++)
#pragma unroll
                for (int nt = 0; nt < 4; nt++)
                    mma8(acc[mt][nt], a[mt], bf[nt]);
        }
        __syncthreads();
    }

#pragma unroll
    for (int mt = 0; mt < 4; mt++) {
        int rr = r0 + wm * 64 + mt * 16 + g;
        float z0 = 1.f / (g_z[rr] + 1e-8f);
        float z1 = 1.f / (g_z[rr + 8] + 1e-8f);
#pragma unroll
        for (int nt = 0; nt < 4; nt++) {
            int d = d0 + wn * 32 + nt * 8 + (t << 1);
            out[(size_t)rr * EMB + d]           = acc[mt][nt][0] * z0;
            out[(size_t)rr * EMB + d + 1]       = acc[mt][nt][1] * z0;
            out[(size_t)(rr + 8) * EMB + d]     = acc[mt][nt][2] * z1;
            out[(size_t)(rr + 8) * EMB + d + 1] = acc[mt][nt][3] * z1;
        }
    }
}

extern "C" void kernel_launch(void* const* d_in, const int* in_sizes, int n_in,
                              void* d_out, int out_size)
{
    (void)in_sizes; (void)n_in; (void)out_size;
    const float* x  = (const float*)d_in[0];
    const float* qp = (const float*)d_in[1];
    const float* kp = (const float*)d_in[2];
    float* out = (float*)d_out;

    s1_proj_exp<<<dim3(8, 256), 256>>>(x, qp, kp);  // logits + exp
    s_z<<<4096, 256>>>();                           // row sums of q'
    s2_kv<<<dim3(8, 4, 8), 256>>>(x);               // kv summaries
    s3_out<<<dim3(8, 256), 256>>>(out);             // numerator + normalize
}